// round 1
// baseline (speedup 1.0000x reference)
#include <cuda_runtime.h>
#include <cuda_bf16.h>

// Problem constants: B=1, H=2, S=128, D=64
#define Sdim 128
#define Ddim 64
#define Hdim 2
#define TWOD 128          // 2*D
#define DD   4096         // D*D
#define ROWS (Hdim * Sdim)   // 256 (h, s) pairs

// Scratch (device globals; no allocation allowed)
__device__ float g_A [ROWS * TWOD];   // Q @ W1[:D]            (256 x 128)
__device__ float g_Bk[ROWS * TWOD];   // K @ W1[D:] + b1       (256 x 128)
__device__ float g_T [ROWS * TWOD];   // sum_i tanh(A_i + Bk_j) (256 x 128)
__device__ float g_U [ROWS * DD];     // T @ W2                 (256 x 4096)

// ---------------------------------------------------------------------------
// K1: A[r,c] = sum_k Q[r,k]*W1[k,c] ;  Bk[r,c] = sum_k K[r,k]*W1[64+k,c] + b1[c]
// grid 512 blocks x 128 threads. blocks [0,256): A, [256,512): Bk
// ---------------------------------------------------------------------------
__global__ void k1_proj(const float* __restrict__ Q, const float* __restrict__ Kin,
                        const float* __restrict__ W1, const float* __restrict__ b1) {
    int b = blockIdx.x;
    int c = threadIdx.x;                 // 0..127
    bool isB = (b >= ROWS);
    int r = isB ? b - ROWS : b;
    const float* x = (isB ? Kin : Q) + r * Ddim;
    const float* W = W1 + (isB ? Ddim * TWOD : 0);
    float acc = isB ? b1[c] : 0.0f;
#pragma unroll
    for (int k = 0; k < Ddim; k++)
        acc = fmaf(x[k], W[k * TWOD + c], acc);
    (isB ? g_Bk : g_A)[r * TWOD + c] = acc;
}

// ---------------------------------------------------------------------------
// K2: T[r,c] = sum_i tanh(A[h,i,c] + Bk[r,c]),  r = h*128 + j
// grid 256 blocks x 128 threads (c = hidden index)
// ---------------------------------------------------------------------------
__global__ void k2_tanh_reduce() {
    int r = blockIdx.x;                  // (h, j)
    int c = threadIdx.x;
    int h = r >> 7;
    float bk = g_Bk[r * TWOD + c];
    const float* Abase = g_A + h * Sdim * TWOD + c;
    float acc0 = 0.f, acc1 = 0.f, acc2 = 0.f, acc3 = 0.f;
#pragma unroll 4
    for (int i = 0; i < Sdim; i += 4) {
        acc0 += tanhf(Abase[(i + 0) * TWOD] + bk);
        acc1 += tanhf(Abase[(i + 1) * TWOD] + bk);
        acc2 += tanhf(Abase[(i + 2) * TWOD] + bk);
        acc3 += tanhf(Abase[(i + 3) * TWOD] + bk);
    }
    g_T[r * TWOD + c] = (acc0 + acc1) + (acc2 + acc3);
}

// ---------------------------------------------------------------------------
// K3: U = T @ W2.  M=256, N=4096, K=128.  BM=64, BN=64, BK=32.
// 256 threads, each computes a 4x4 micro-tile.
// grid: (N/64=64, M/64=4)
// ---------------------------------------------------------------------------
__global__ void k3_gemm(const float* __restrict__ W2) {
    __shared__ float Ts[64 * 32];    // [m][k]
    __shared__ float Ws[32 * 64];    // [k][n]
    int bm = blockIdx.y, bn = blockIdx.x;
    int tid = threadIdx.x;           // 0..255
    int tx = tid & 15;               // n-group
    int ty = tid >> 4;               // m-group

    float acc[4][4];
#pragma unroll
    for (int i = 0; i < 4; i++)
#pragma unroll
        for (int j = 0; j < 4; j++) acc[i][j] = 0.f;

#pragma unroll
    for (int kt = 0; kt < 4; kt++) {
        // load T tile: 64x32 floats = 512 float4, 2 per thread
#pragma unroll
        for (int v = 0; v < 2; v++) {
            int i4 = tid * 2 + v;
            int row = i4 >> 3, col4 = i4 & 7;
            ((float4*)Ts)[i4] =
                *(const float4*)(g_T + (bm * 64 + row) * TWOD + kt * 32 + col4 * 4);
        }
        // load W2 tile: 32x64 floats = 512 float4, 2 per thread
#pragma unroll
        for (int v = 0; v < 2; v++) {
            int i4 = tid * 2 + v;
            int krow = i4 >> 4, col4 = i4 & 15;
            ((float4*)Ws)[i4] =
                *(const float4*)(W2 + (kt * 32 + krow) * DD + bn * 64 + col4 * 4);
        }
        __syncthreads();

#pragma unroll
        for (int kk = 0; kk < 32; kk++) {
            float a0 = Ts[(ty * 4 + 0) * 32 + kk];
            float a1 = Ts[(ty * 4 + 1) * 32 + kk];
            float a2 = Ts[(ty * 4 + 2) * 32 + kk];
            float a3 = Ts[(ty * 4 + 3) * 32 + kk];
            float4 bvec = ((const float4*)Ws)[kk * 16 + tx];
            acc[0][0] = fmaf(a0, bvec.x, acc[0][0]);
            acc[0][1] = fmaf(a0, bvec.y, acc[0][1]);
            acc[0][2] = fmaf(a0, bvec.z, acc[0][2]);
            acc[0][3] = fmaf(a0, bvec.w, acc[0][3]);
            acc[1][0] = fmaf(a1, bvec.x, acc[1][0]);
            acc[1][1] = fmaf(a1, bvec.y, acc[1][1]);
            acc[1][2] = fmaf(a1, bvec.z, acc[1][2]);
            acc[1][3] = fmaf(a1, bvec.w, acc[1][3]);
            acc[2][0] = fmaf(a2, bvec.x, acc[2][0]);
            acc[2][1] = fmaf(a2, bvec.y, acc[2][1]);
            acc[2][2] = fmaf(a2, bvec.z, acc[2][2]);
            acc[2][3] = fmaf(a2, bvec.w, acc[2][3]);
            acc[3][0] = fmaf(a3, bvec.x, acc[3][0]);
            acc[3][1] = fmaf(a3, bvec.y, acc[3][1]);
            acc[3][2] = fmaf(a3, bvec.z, acc[3][2]);
            acc[3][3] = fmaf(a3, bvec.w, acc[3][3]);
        }
        __syncthreads();
    }

#pragma unroll
    for (int i = 0; i < 4; i++) {
        float4 o = make_float4(acc[i][0], acc[i][1], acc[i][2], acc[i][3]);
        *(float4*)(g_U + (bm * 64 + ty * 4 + i) * DD + bn * 64 + tx * 4) = o;
    }
}

// ---------------------------------------------------------------------------
// K4: out[r,d] = sum_e ( U[r, d*64+e]/S + b2[d*64+e] ) * K[r,e]
// grid 256 blocks x 128 threads. Row of U staged in smem (fused bias+scale).
// ---------------------------------------------------------------------------
__global__ void k4_contract(const float* __restrict__ Kin,
                            const float* __restrict__ b2,
                            float* __restrict__ out) {
    __shared__ float Urow[DD];
    __shared__ float Ks[Ddim];
    int r = blockIdx.x;
    int t = threadIdx.x;                 // 0..127
    const float invS = 1.0f / (float)Sdim;

    const float4* Uv = (const float4*)(g_U + r * DD);
    const float4* Bv = (const float4*)b2;
#pragma unroll
    for (int n4 = t; n4 < DD / 4; n4 += 128) {
        float4 u = Uv[n4];
        float4 bb = Bv[n4];
        u.x = fmaf(u.x, invS, bb.x);
        u.y = fmaf(u.y, invS, bb.y);
        u.z = fmaf(u.z, invS, bb.z);
        u.w = fmaf(u.w, invS, bb.w);
        ((float4*)Urow)[n4] = u;
    }
    if (t < Ddim) Ks[t] = Kin[r * Ddim + t];
    __syncthreads();

    if (t < Ddim) {
        float acc = 0.f;
#pragma unroll
        for (int e0 = 0; e0 < Ddim; e0++) {
            int e = (e0 + t) & (Ddim - 1);   // skew: bank-conflict-free
            acc = fmaf(Urow[t * Ddim + e], Ks[e], acc);
        }
        out[r * Ddim + t] = acc;
    }
}

// ---------------------------------------------------------------------------
extern "C" void kernel_launch(void* const* d_in, const int* in_sizes, int n_in,
                              void* d_out, int out_size) {
    const float* Q   = (const float*)d_in[0];
    const float* Kin = (const float*)d_in[1];
    const float* W1  = (const float*)d_in[2];
    const float* b1  = (const float*)d_in[3];
    const float* W2  = (const float*)d_in[4];
    const float* b2  = (const float*)d_in[5];
    float* out = (float*)d_out;

    k1_proj<<<2 * ROWS, TWOD>>>(Q, Kin, W1, b1);
    k2_tanh_reduce<<<ROWS, TWOD>>>();
    k3_gemm<<<dim3(DD / 64, ROWS / 64), 256>>>(W2);
    k4_contract<<<ROWS, 128>>>(Kin, b2, out);
}

// round 2
// speedup vs baseline: 1.5649x; 1.5649x over previous
#include <cuda_runtime.h>
#include <cuda_bf16.h>

// Problem constants: B=1, H=2, S=128, D=64
#define Sdim 128
#define Ddim 64
#define Hdim 2
#define TWOD 128          // 2*D
#define DD   4096         // D*D
#define ROWS (Hdim * Sdim)   // 256 (h, s) pairs

// Scratch (device globals; no allocation allowed)
__device__ float g_A [ROWS * TWOD];   // Q @ W1[:D]            (256 x 128)
__device__ float g_Bk[ROWS * TWOD];   // K @ W1[D:] + b1       (256 x 128)
__device__ float g_T [ROWS * TWOD];   // sum_i tanh(A_i + Bk_j) (256 x 128)

__device__ __forceinline__ float tanh_approx(float x) {
    float y;
    asm("tanh.approx.f32 %0, %1;" : "=f"(y) : "f"(x));
    return y;
}

// ---------------------------------------------------------------------------
// K1: A[r,c] = sum_k Q[r,k]*W1[k,c] ;  Bk[r,c] = sum_k K[r,k]*W1[64+k,c] + b1[c]
// grid 512 blocks x 128 threads. blocks [0,256): A, [256,512): Bk
// ---------------------------------------------------------------------------
__global__ void k1_proj(const float* __restrict__ Q, const float* __restrict__ Kin,
                        const float* __restrict__ W1, const float* __restrict__ b1) {
    int b = blockIdx.x;
    int c = threadIdx.x;                 // 0..127
    bool isB = (b >= ROWS);
    int r = isB ? b - ROWS : b;
    const float* x = (isB ? Kin : Q) + r * Ddim;
    const float* W = W1 + (isB ? Ddim * TWOD : 0);
    float acc = isB ? b1[c] : 0.0f;
#pragma unroll
    for (int k = 0; k < Ddim; k++)
        acc = fmaf(x[k], W[k * TWOD + c], acc);
    (isB ? g_Bk : g_A)[r * TWOD + c] = acc;
}

// ---------------------------------------------------------------------------
// K2: T[r,c] = sum_i tanh(A[h,i,c] + Bk[r,c]),  r = h*128 + j
// grid 256 blocks x 128 threads (c = hidden index). HW tanh.approx.
// ---------------------------------------------------------------------------
__global__ void k2_tanh_reduce() {
    int r = blockIdx.x;                  // (h, j)
    int c = threadIdx.x;
    int h = r >> 7;
    float bk = g_Bk[r * TWOD + c];
    const float* Abase = g_A + h * Sdim * TWOD + c;
    float acc0 = 0.f, acc1 = 0.f, acc2 = 0.f, acc3 = 0.f;
#pragma unroll 8
    for (int i = 0; i < Sdim; i += 4) {
        acc0 += tanh_approx(Abase[(i + 0) * TWOD] + bk);
        acc1 += tanh_approx(Abase[(i + 1) * TWOD] + bk);
        acc2 += tanh_approx(Abase[(i + 2) * TWOD] + bk);
        acc3 += tanh_approx(Abase[(i + 3) * TWOD] + bk);
    }
    g_T[r * TWOD + c] = (acc0 + acc1) + (acc2 + acc3);
}

// ---------------------------------------------------------------------------
// K3 (fused): tile of U = T @ W2 computed in registers, then contracted
// against K in the epilogue:
//   out[m, d=bn] = sum_e (Utile[m,e]/S + b2[d*64+e]) * K[m,e]
// M=256, N=4096, K=128.  BM=64, BN=64 (exactly one d per block), BK=32.
// 256 threads, 4x4 micro-tile each. grid: (64, 4).
// ---------------------------------------------------------------------------
__global__ void k3_gemm_fused(const float* __restrict__ W2,
                              const float* __restrict__ Kin,
                              const float* __restrict__ b2,
                              float* __restrict__ out) {
    __shared__ float Ts[64 * 32];    // [m][k]
    __shared__ float Ws[32 * 64];    // [k][n]
    __shared__ float Ksh[64 * Ddim]; // K rows for this m-block (16KB)
    int bm = blockIdx.y, bn = blockIdx.x;
    int tid = threadIdx.x;           // 0..255
    int tx = tid & 15;               // e-group (4 cols)
    int ty = tid >> 4;               // m-group (4 rows)

    // Stage K rows for this m-block (used only after mainloop's last sync)
#pragma unroll
    for (int v = 0; v < 4; v++) {
        int i4 = tid + v * 256;              // 1024 float4s
        int row = i4 >> 4, col4 = i4 & 15;
        ((float4*)Ksh)[i4] =
            *(const float4*)(Kin + (bm * 64 + row) * Ddim + col4 * 4);
    }

    float acc[4][4];
#pragma unroll
    for (int i = 0; i < 4; i++)
#pragma unroll
        for (int j = 0; j < 4; j++) acc[i][j] = 0.f;

#pragma unroll
    for (int kt = 0; kt < 4; kt++) {
        // load T tile: 64x32 floats = 512 float4, 2 per thread
#pragma unroll
        for (int v = 0; v < 2; v++) {
            int i4 = tid * 2 + v;
            int row = i4 >> 3, col4 = i4 & 7;
            ((float4*)Ts)[i4] =
                *(const float4*)(g_T + (bm * 64 + row) * TWOD + kt * 32 + col4 * 4);
        }
        // load W2 tile: 32x64 floats = 512 float4, 2 per thread
#pragma unroll
        for (int v = 0; v < 2; v++) {
            int i4 = tid * 2 + v;
            int krow = i4 >> 4, col4 = i4 & 15;
            ((float4*)Ws)[i4] =
                *(const float4*)(W2 + (kt * 32 + krow) * DD + bn * 64 + col4 * 4);
        }
        __syncthreads();

#pragma unroll
        for (int kk = 0; kk < 32; kk++) {
            float a0 = Ts[(ty * 4 + 0) * 32 + kk];
            float a1 = Ts[(ty * 4 + 1) * 32 + kk];
            float a2 = Ts[(ty * 4 + 2) * 32 + kk];
            float a3 = Ts[(ty * 4 + 3) * 32 + kk];
            float4 bvec = ((const float4*)Ws)[kk * 16 + tx];
            acc[0][0] = fmaf(a0, bvec.x, acc[0][0]);
            acc[0][1] = fmaf(a0, bvec.y, acc[0][1]);
            acc[0][2] = fmaf(a0, bvec.z, acc[0][2]);
            acc[0][3] = fmaf(a0, bvec.w, acc[0][3]);
            acc[1][0] = fmaf(a1, bvec.x, acc[1][0]);
            acc[1][1] = fmaf(a1, bvec.y, acc[1][1]);
            acc[1][2] = fmaf(a1, bvec.z, acc[1][2]);
            acc[1][3] = fmaf(a1, bvec.w, acc[1][3]);
            acc[2][0] = fmaf(a2, bvec.x, acc[2][0]);
            acc[2][1] = fmaf(a2, bvec.y, acc[2][1]);
            acc[2][2] = fmaf(a2, bvec.z, acc[2][2]);
            acc[2][3] = fmaf(a2, bvec.w, acc[2][3]);
            acc[3][0] = fmaf(a3, bvec.x, acc[3][0]);
            acc[3][1] = fmaf(a3, bvec.y, acc[3][1]);
            acc[3][2] = fmaf(a3, bvec.z, acc[3][2]);
            acc[3][3] = fmaf(a3, bvec.w, acc[3][3]);
        }
        __syncthreads();
    }

    // Epilogue: contract e-dimension (columns of this tile) against K rows.
    // This thread owns m-rows (bm*64 + ty*4 + i), e-cols (tx*4 + j).
    const float invS = 1.0f / (float)Sdim;
    float4 bb = *(const float4*)(b2 + bn * 64 + tx * 4);
#pragma unroll
    for (int i = 0; i < 4; i++) {
        float4 kv = *(const float4*)(Ksh + (ty * 4 + i) * Ddim + tx * 4);
        float v0 = fmaf(acc[i][0], invS, bb.x);
        float v1 = fmaf(acc[i][1], invS, bb.y);
        float v2 = fmaf(acc[i][2], invS, bb.z);
        float v3 = fmaf(acc[i][3], invS, bb.w);
        float p = v0 * kv.x + v1 * kv.y + v2 * kv.z + v3 * kv.w;
        // reduce across the 16 tx lanes (contiguous lanes within half-warp)
#pragma unroll
        for (int off = 1; off < 16; off <<= 1)
            p += __shfl_xor_sync(0xffffffffu, p, off, 32);
        if (tx == 0)
            out[(bm * 64 + ty * 4 + i) * Ddim + bn] = p;
    }
}

// ---------------------------------------------------------------------------
extern "C" void kernel_launch(void* const* d_in, const int* in_sizes, int n_in,
                              void* d_out, int out_size) {
    const float* Q   = (const float*)d_in[0];
    const float* Kin = (const float*)d_in[1];
    const float* W1  = (const float*)d_in[2];
    const float* b1  = (const float*)d_in[3];
    const float* W2  = (const float*)d_in[4];
    const float* b2  = (const float*)d_in[5];
    float* out = (float*)d_out;

    k1_proj<<<2 * ROWS, TWOD>>>(Q, Kin, W1, b1);
    k2_tanh_reduce<<<ROWS, TWOD>>>();
    k3_gemm_fused<<<dim3(DD / 64, ROWS / 64), 256>>>(W2, Kin, b2, out);
}

// round 3
// speedup vs baseline: 1.7083x; 1.0917x over previous
#include <cuda_runtime.h>
#include <cuda_bf16.h>

// Problem constants: B=1, H=2, S=128, D=64
#define Sdim 128
#define Ddim 64
#define Hdim 2
#define TWOD 128          // 2*D
#define DD   4096         // D*D
#define ROWS (Hdim * Sdim)   // 256 (h, s) pairs

typedef unsigned long long ull;

// Scratch (device globals; no allocation allowed)
__device__ float g_A [ROWS * TWOD];   // Q @ W1[:D]            (256 x 128)
__device__ float g_Bk[ROWS * TWOD];   // K @ W1[D:] + b1       (256 x 128)
__device__ float g_T [ROWS * TWOD];   // sum_i tanh(A_i + Bk_j) (256 x 128)

__device__ __forceinline__ float tanh_approx(float x) {
    float y;
    asm("tanh.approx.f32 %0, %1;" : "=f"(y) : "f"(x));
    return y;
}
__device__ __forceinline__ ull fma2(ull a, ull b, ull c) {
    ull d;
    asm("fma.rn.f32x2 %0, %1, %2, %3;" : "=l"(d) : "l"(a), "l"(b), "l"(c));
    return d;
}
__device__ __forceinline__ ull pack2(float x, float y) {
    ull r;
    asm("mov.b64 %0, {%1, %2};" : "=l"(r) : "f"(x), "f"(y));
    return r;
}
__device__ __forceinline__ void unpack2(ull v, float& x, float& y) {
    asm("mov.b64 {%0, %1}, %2;" : "=f"(x), "=f"(y) : "l"(v));
}

// ---------------------------------------------------------------------------
// K1: A[r,c] = sum_k Q[r,k]*W1[k,c] ;  Bk[r,c] = sum_k K[r,k]*W1[64+k,c]+b1[c]
// grid 128 blocks x 128 threads. block = (rowgrp of 4 rows) x (A|Bk half).
// 4 rows share the streamed W1 column -> 4 indep acc chains, high MLP.
// ---------------------------------------------------------------------------
__global__ void __launch_bounds__(128, 4)
k1_proj(const float* __restrict__ Q, const float* __restrict__ Kin,
        const float* __restrict__ W1, const float* __restrict__ b1) {
    __shared__ float x_s[4 * Ddim];          // 4 input rows
    int b = blockIdx.x;
    int c = threadIdx.x;                     // 0..127 column
    bool isB = (b & 1);
    int r0 = (b >> 1) * 4;
    const float* src = (isB ? Kin : Q) + r0 * Ddim;
    const float* W = W1 + (isB ? Ddim * TWOD : 0);

    x_s[c] = src[c];
    x_s[c + 128] = src[c + 128];
    __syncthreads();

    float acc0, acc1, acc2, acc3;
    acc0 = acc1 = acc2 = acc3 = isB ? b1[c] : 0.0f;
#pragma unroll
    for (int k = 0; k < Ddim; k++) {
        float w = W[k * TWOD + c];
        acc0 = fmaf(x_s[0 * Ddim + k], w, acc0);
        acc1 = fmaf(x_s[1 * Ddim + k], w, acc1);
        acc2 = fmaf(x_s[2 * Ddim + k], w, acc2);
        acc3 = fmaf(x_s[3 * Ddim + k], w, acc3);
    }
    float* dst = (isB ? g_Bk : g_A) + r0 * TWOD + c;
    dst[0 * TWOD] = acc0;
    dst[1 * TWOD] = acc1;
    dst[2 * TWOD] = acc2;
    dst[3 * TWOD] = acc3;
}

// ---------------------------------------------------------------------------
// K2: T[r,c] = sum_i tanh(A[h,i,c] + Bk[r,c]),  r = h*128 + j
// grid 256 x 128. 8 loads batched ahead of the MUFU.TANH chain.
// ---------------------------------------------------------------------------
__global__ void __launch_bounds__(128, 4) k2_tanh_reduce() {
    int r = blockIdx.x;                  // (h, j)
    int c = threadIdx.x;
    int h = r >> 7;
    float bk = g_Bk[r * TWOD + c];
    const float* Abase = g_A + h * Sdim * TWOD + c;
    float acc0 = 0.f, acc1 = 0.f, acc2 = 0.f, acc3 = 0.f;
#pragma unroll
    for (int i = 0; i < Sdim; i += 8) {
        float a0 = Abase[(i + 0) * TWOD];
        float a1 = Abase[(i + 1) * TWOD];
        float a2 = Abase[(i + 2) * TWOD];
        float a3 = Abase[(i + 3) * TWOD];
        float a4 = Abase[(i + 4) * TWOD];
        float a5 = Abase[(i + 5) * TWOD];
        float a6 = Abase[(i + 6) * TWOD];
        float a7 = Abase[(i + 7) * TWOD];
        acc0 += tanh_approx(a0 + bk);
        acc1 += tanh_approx(a1 + bk);
        acc2 += tanh_approx(a2 + bk);
        acc3 += tanh_approx(a3 + bk);
        acc0 += tanh_approx(a4 + bk);
        acc1 += tanh_approx(a5 + bk);
        acc2 += tanh_approx(a6 + bk);
        acc3 += tanh_approx(a7 + bk);
    }
    g_T[r * TWOD + c] = (acc0 + acc1) + (acc2 + acc3);
}

// ---------------------------------------------------------------------------
// K3 (fused, f32x2): tile of U = T @ W2 in packed-pair registers, contracted
// against K in epilogue:
//   out[m, d=bn] = sum_e (Utile[m,e]/S + b2[d*64+e]) * K[m,e]
// M=256, N=4096, K=128.  BM=64, BN=64 (one d per block), BK=32.
// 128 threads: tx in [0,16) -> 4 e-cols; ty in [0,8) -> 8 m-rows (4 pairs).
// T and K stored m-transposed in smem so m-pairs load as one LDS.64.
// grid: (64, 4).
// ---------------------------------------------------------------------------
#define TSTRIDE 66   // even pad: 8B alignment for pair loads, reduced conflicts

__global__ void __launch_bounds__(128, 4)
k3_gemm_fused(const float* __restrict__ W2,
              const float* __restrict__ Kin,
              const float* __restrict__ b2,
              float* __restrict__ out) {
    __shared__ float Tst[32 * TSTRIDE];   // [kk][m] transposed T tile
    __shared__ float Ws [32 * 64];        // [kk][n]
    __shared__ float Kst[64 * TSTRIDE];   // [e][m] transposed K rows
    int bm = blockIdx.y, bn = blockIdx.x;
    int tid = threadIdx.x;                // 0..127
    int tx = tid & 15;                    // e-group (4 cols)
    int ty = tid >> 4;                    // m-group (8 rows)

    // Stage K rows (transposed): 64 m x 64 e
#pragma unroll
    for (int v = 0; v < 8; v++) {
        int i4 = tid + v * 128;           // 1024 float4
        int m = i4 >> 4, e4 = i4 & 15;
        float4 f = *(const float4*)(Kin + (bm * 64 + m) * Ddim + e4 * 4);
        Kst[(e4 * 4 + 0) * TSTRIDE + m] = f.x;
        Kst[(e4 * 4 + 1) * TSTRIDE + m] = f.y;
        Kst[(e4 * 4 + 2) * TSTRIDE + m] = f.z;
        Kst[(e4 * 4 + 3) * TSTRIDE + m] = f.w;
    }

    ull acc[4][4];
#pragma unroll
    for (int p = 0; p < 4; p++)
#pragma unroll
        for (int c = 0; c < 4; c++) acc[p][c] = 0ull;

#pragma unroll
    for (int kt = 0; kt < 4; kt++) {
        // stage T tile transposed: 64 m x 32 k
#pragma unroll
        for (int v = 0; v < 4; v++) {
            int i4 = tid + v * 128;       // 512 float4
            int m = i4 >> 3, kq = i4 & 7;
            float4 f = *(const float4*)(g_T + (bm * 64 + m) * TWOD + kt * 32 + kq * 4);
            Tst[(kq * 4 + 0) * TSTRIDE + m] = f.x;
            Tst[(kq * 4 + 1) * TSTRIDE + m] = f.y;
            Tst[(kq * 4 + 2) * TSTRIDE + m] = f.z;
            Tst[(kq * 4 + 3) * TSTRIDE + m] = f.w;
        }
        // stage W2 tile: 32 k x 64 n (row-major)
#pragma unroll
        for (int v = 0; v < 4; v++) {
            int i4 = tid + v * 128;       // 512 float4
            int kk = i4 >> 4, n4 = i4 & 15;
            ((float4*)Ws)[i4] =
                *(const float4*)(W2 + (kt * 32 + kk) * DD + bn * 64 + n4 * 4);
        }
        __syncthreads();

#pragma unroll
        for (int kk = 0; kk < 32; kk++) {
            const float* trow = Tst + kk * TSTRIDE + ty * 8;
            ull a0 = *(const ull*)(trow + 0);   // (m0,m1)
            ull a1 = *(const ull*)(trow + 2);
            ull a2 = *(const ull*)(trow + 4);
            ull a3 = *(const ull*)(trow + 6);
            float4 bv = *(const float4*)(Ws + kk * 64 + tx * 4);
            ull b0 = pack2(bv.x, bv.x);
            ull b1 = pack2(bv.y, bv.y);
            ull b2p = pack2(bv.z, bv.z);
            ull b3 = pack2(bv.w, bv.w);
            acc[0][0] = fma2(a0, b0, acc[0][0]);
            acc[0][1] = fma2(a0, b1, acc[0][1]);
            acc[0][2] = fma2(a0, b2p, acc[0][2]);
            acc[0][3] = fma2(a0, b3, acc[0][3]);
            acc[1][0] = fma2(a1, b0, acc[1][0]);
            acc[1][1] = fma2(a1, b1, acc[1][1]);
            acc[1][2] = fma2(a1, b2p, acc[1][2]);
            acc[1][3] = fma2(a1, b3, acc[1][3]);
            acc[2][0] = fma2(a2, b0, acc[2][0]);
            acc[2][1] = fma2(a2, b1, acc[2][1]);
            acc[2][2] = fma2(a2, b2p, acc[2][2]);
            acc[2][3] = fma2(a2, b3, acc[2][3]);
            acc[3][0] = fma2(a3, b0, acc[3][0]);
            acc[3][1] = fma2(a3, b1, acc[3][1]);
            acc[3][2] = fma2(a3, b2p, acc[3][2]);
            acc[3][3] = fma2(a3, b3, acc[3][3]);
        }
        __syncthreads();
    }

    // Epilogue: v = acc/S + b2 ; out pair += v * K (packed over m-pair),
    // then 16-lane shuffle reduce over e-groups.
    const float invS = 1.0f / (float)Sdim;
    ull invS2 = pack2(invS, invS);
    float4 bbv = *(const float4*)(b2 + bn * 64 + tx * 4);
    ull bb[4] = { pack2(bbv.x, bbv.x), pack2(bbv.y, bbv.y),
                  pack2(bbv.z, bbv.z), pack2(bbv.w, bbv.w) };
#pragma unroll
    for (int p = 0; p < 4; p++) {
        ull sum = 0ull;
#pragma unroll
        for (int c = 0; c < 4; c++) {
            ull v = fma2(acc[p][c], invS2, bb[c]);
            ull kv = *(const ull*)(Kst + (tx * 4 + c) * TSTRIDE + ty * 8 + 2 * p);
            sum = fma2(v, kv, sum);
        }
        float s0, s1;
        unpack2(sum, s0, s1);
#pragma unroll
        for (int off = 1; off < 16; off <<= 1) {
            s0 += __shfl_xor_sync(0xffffffffu, s0, off, 32);
            s1 += __shfl_xor_sync(0xffffffffu, s1, off, 32);
        }
        if (tx == 0) {
            int m0 = bm * 64 + ty * 8 + 2 * p;
            out[m0 * Ddim + bn] = s0;
            out[(m0 + 1) * Ddim + bn] = s1;
        }
    }
}

// ---------------------------------------------------------------------------
extern "C" void kernel_launch(void* const* d_in, const int* in_sizes, int n_in,
                              void* d_out, int out_size) {
    const float* Q   = (const float*)d_in[0];
    const float* Kin = (const float*)d_in[1];
    const float* W1  = (const float*)d_in[2];
    const float* b1  = (const float*)d_in[3];
    const float* W2  = (const float*)d_in[4];
    const float* b2  = (const float*)d_in[5];
    float* out = (float*)d_out;

    k1_proj<<<128, 128>>>(Q, Kin, W1, b1);
    k2_tanh_reduce<<<ROWS, TWOD>>>();
    k3_gemm_fused<<<dim3(Ddim, ROWS / 64), 128>>>(W2, Kin, b2, out);
}